// round 1
// baseline (speedup 1.0000x reference)
#include <cuda_runtime.h>

// CoExCostVolume: cost[b,d,h,w] = sum_c x[b,c,h,w] * y[b,c,h,w-d], zero for w<d.
// B=8, C=96, H=128, W=416, D=49 (maxdisp 48 + 1).
//
// Strategy: one CTA per (b,h) row (1024 CTAs). Stage c-chunks of 48 channels of
// x (416 wide) and left-zero-padded y (464 wide) in shared memory with a
// +1-per-8 skew so lane-stride-8 reads are bank-conflict-free. Each thread
// computes a 7(d) x 8(w) register tile: per channel it loads 8 x values and a
// 14-wide sliding window of y, issuing 56 FFMAs. FMA-pipe bound by design.

#define B_DIM 8
#define C_DIM 96
#define H_DIM 128
#define W_DIM 416
#define D_DIM 49

#define CC 48              // channels per smem chunk (2 chunks)
#define PADW 48            // left zero pad on y
#define YW (W_DIM + PADW)  // 464
#define XSTRIDE 468        // >= sidx(415)+1 = 467
#define YSTRIDE 524        // >= sidx(463)+1 = 521
#define NTHREADS 384
#define SMEM_BYTES ((CC * XSTRIDE + CC * YSTRIDE) * 4)

__device__ __forceinline__ int sidx(int p) { return p + (p >> 3); }

__global__ void __launch_bounds__(NTHREADS, 1)
coex_cost_kernel(const float* __restrict__ x,
                 const float* __restrict__ y,
                 float* __restrict__ out) {
    extern __shared__ float sm[];
    float* xs = sm;                  // [CC][XSTRIDE] skewed
    float* ys = sm + CC * XSTRIDE;   // [CC][YSTRIDE] skewed, left 48 zeros

    const int bid = blockIdx.x;
    const int b = bid >> 7;          // /128
    const int h = bid & 127;

    const int tid = threadIdx.x;
    const int dth = tid / 52;        // 0..7 (7 is stage-only)
    const int wth = tid - dth * 52;  // 0..51
    const bool active = (dth < 7);
    const int d0 = dth * 7;
    const int w0 = wth * 8;

    float acc[7][8];
#pragma unroll
    for (int i = 0; i < 7; i++)
#pragma unroll
        for (int j = 0; j < 8; j++) acc[i][j] = 0.0f;

    // Per-thread skewed element offsets (constant across channels / chunks).
    int xoff[8];
#pragma unroll
    for (int j = 0; j < 8; j++) xoff[j] = sidx(w0 + j);
    int yoff[14];
    const int ybase = w0 - d0 + 42;  // padded coord of window start (>= 0)
#pragma unroll
    for (int k = 0; k < 14; k++) yoff[k] = sidx(ybase + k);

    const long row_base = ((long)b * C_DIM) * H_DIM + h;  // add c*H_DIM, then *W

    for (int chunk = 0; chunk < 2; chunk++) {
        const int cb = chunk * CC;
        __syncthreads();  // protect smem from previous chunk's readers

        // ---- stage x and y chunk into skewed smem ----
        for (int idx = tid; idx < CC * W_DIM; idx += NTHREADS) {
            int c = idx / W_DIM;
            int w = idx - c * W_DIM;
            long g = (row_base + (long)(cb + c) * H_DIM) * W_DIM + w;
            xs[c * XSTRIDE + sidx(w)] = x[g];
            ys[c * YSTRIDE + sidx(PADW + w)] = y[g];
        }
        for (int idx = tid; idx < CC * PADW; idx += NTHREADS) {
            int c = idx / PADW;
            int p = idx - c * PADW;
            ys[c * YSTRIDE + sidx(p)] = 0.0f;
        }
        __syncthreads();

        // ---- compute ----
        if (active) {
#pragma unroll 2
            for (int c = 0; c < CC; c++) {
                const float* xr = xs + c * XSTRIDE;
                const float* yr = ys + c * YSTRIDE;
                float xv[8], yv[14];
#pragma unroll
                for (int j = 0; j < 8; j++) xv[j] = xr[xoff[j]];
#pragma unroll
                for (int k = 0; k < 14; k++) yv[k] = yr[yoff[k]];
#pragma unroll
                for (int i = 0; i < 7; i++)
#pragma unroll
                    for (int j = 0; j < 8; j++)
                        acc[i][j] = fmaf(xv[j], yv[j + 6 - i], acc[i][j]);
            }
        }
    }

    // ---- write 7x8 tile, two float4 stores per d ----
    if (active) {
#pragma unroll
        for (int i = 0; i < 7; i++) {
            const int d = d0 + i;
            float* o = out + (((long)b * D_DIM + d) * H_DIM + h) * W_DIM + w0;
            float4 v0 = make_float4(acc[i][0], acc[i][1], acc[i][2], acc[i][3]);
            float4 v1 = make_float4(acc[i][4], acc[i][5], acc[i][6], acc[i][7]);
            *reinterpret_cast<float4*>(o) = v0;
            *reinterpret_cast<float4*>(o + 4) = v1;
        }
    }
}

extern "C" void kernel_launch(void* const* d_in, const int* in_sizes, int n_in,
                              void* d_out, int out_size) {
    const float* x = (const float*)d_in[0];
    const float* y = (const float*)d_in[1];
    float* out = (float*)d_out;

    cudaFuncSetAttribute(coex_cost_kernel,
                         cudaFuncAttributeMaxDynamicSharedMemorySize, SMEM_BYTES);

    dim3 grid(B_DIM * H_DIM);  // 1024
    coex_cost_kernel<<<grid, NTHREADS, SMEM_BYTES>>>(x, y, out);
}

// round 2
// speedup vs baseline: 1.3024x; 1.3024x over previous
#include <cuda_runtime.h>

// CoExCostVolume: cost[b,d,h,w] = sum_c x[b,c,h,w] * y[b,c,h,w-d], zero for w<d.
// B=8, C=96, H=128, W=416, D=49.
//
// One CTA per (b,h) row. cp.async double-buffered channel chunks (24 ch each),
// skewed (+1 per 8 floats) smem for conflict-free scalar LDS, and packed
// fma.rn.f32x2 accumulation (7d x 8w tile -> 28 packed FMAs per channel).

#define B_DIM 8
#define C_DIM 96
#define H_DIM 128
#define W_DIM 416
#define D_DIM 49
#define HW (H_DIM * W_DIM)

#define CC 24                 // channels per chunk
#define NC 4                  // chunks (CC*NC = 96)
#define PADW 48
#define XSTRIDE 468           // >= sidx(415)+1
#define YSTRIDE 524           // >= sidx(463)+1
#define XSZ (CC * XSTRIDE)
#define YSZ (CC * YSTRIDE)
#define BUFSZ (XSZ + YSZ)     // floats per buffer
#define NTHREADS 384
#define SMEM_BYTES (2 * BUFSZ * 4)

typedef unsigned long long ull;

__device__ __forceinline__ int sidx(int p) { return p + (p >> 3); }

__device__ __forceinline__ void cp4(float* dst_smem, const float* src) {
    unsigned sdst = (unsigned)__cvta_generic_to_shared(dst_smem);
    asm volatile("cp.async.ca.shared.global [%0], [%1], 4;\n" ::"r"(sdst), "l"(src));
}
__device__ __forceinline__ ull pk(float lo, float hi) {
    ull r; asm("mov.b64 %0, {%1, %2};" : "=l"(r) : "f"(lo), "f"(hi)); return r;
}
__device__ __forceinline__ void fma2(ull& d, ull a, ull b) {
    asm("fma.rn.f32x2 %0, %1, %2, %0;" : "+l"(d) : "l"(a), "l"(b));
}
__device__ __forceinline__ float2 upk(ull p) {
    float2 v; asm("mov.b64 {%0, %1}, %2;" : "=f"(v.x), "=f"(v.y) : "l"(p)); return v;
}

__global__ void __launch_bounds__(NTHREADS, 1)
coex_cost_kernel(const float* __restrict__ x,
                 const float* __restrict__ y,
                 float* __restrict__ out) {
    extern __shared__ float sm[];

    const int bid = blockIdx.x;
    const int b = bid >> 7;
    const int h = bid & 127;
    const int tid = threadIdx.x;

    const int dth = tid / 52;        // 0..7 (7 = staging-only)
    const int wth = tid - dth * 52;  // 0..51
    const bool active = (dth < 7);
    const int d0 = dth * 7;
    const int w0 = wth * 8;

    // ---- zero y pad regions once (both buffers) ----
    // pads live at ys row offsets [0, 54): sidx(0..47) subset of [0,53].
    for (int i = tid; i < 2 * CC * 54; i += NTHREADS) {
        int br = i / 54;             // 0..47 (buffer*CC + row)
        int p = i - br * 54;
        int buf = br / CC;
        int c = br - buf * CC;
        sm[buf * BUFSZ + XSZ + c * YSTRIDE + p] = 0.0f;
    }

    // ---- per-thread compute offsets ----
    int yoff[14];
    {
        int yb = w0 - (active ? d0 : 42) + 42;  // >= 0 always
#pragma unroll
        for (int k = 0; k < 14; k++) yoff[k] = sidx(yb + k);
    }
    const int xb = sidx(w0);

    ull acc[28];
#pragma unroll
    for (int i = 0; i < 28; i++) acc[i] = 0ull;

    // global base for this (b,h) row at chunk 0
    const long gbase = ((long)(b * C_DIM) * H_DIM + h) * W_DIM;

    // ---- staging helper (inlined manually via lambda-ish macro loop) ----
    // Each chunk: CC*W elements per array, 26 per thread.
    auto stage = [&](int k) {
        const float* xg = x + gbase + (long)k * CC * HW + tid;
        const float* yg = y + gbase + (long)k * CC * HW + tid;
        float* xs = sm + (k & 1) * BUFSZ;
        float* ys = xs + XSZ;
        int c = 0, w = tid;  // tid < 416 so c starts 0
        int crowx = 0, crowy = 0;
#pragma unroll 2
        for (int it = 0; it < (CC * W_DIM) / NTHREADS; it++) {
            int sw = sidx(w);
            cp4(xs + crowx + sw, xg);
            cp4(ys + crowy + sw + 54, yg);  // sidx(48+w) = sidx(w)+54
            w += NTHREADS;
            long adv = NTHREADS;
            if (w >= W_DIM) {
                w -= W_DIM; c++;
                crowx += XSTRIDE; crowy += YSTRIDE;
                adv += HW - W_DIM;
            }
            xg += adv; yg += adv;
        }
    };

    stage(0);
    asm volatile("cp.async.commit_group;\n");

    for (int k = 0; k < NC; k++) {
        if (k + 1 < NC) {
            stage(k + 1);
            asm volatile("cp.async.commit_group;\n");
            asm volatile("cp.async.wait_group 1;\n" ::: "memory");
        } else {
            asm volatile("cp.async.wait_group 0;\n" ::: "memory");
        }
        __syncthreads();

        if (active) {
            const float* xr = sm + (k & 1) * BUFSZ + xb;
            const float* yr = sm + (k & 1) * BUFSZ + XSZ;
#pragma unroll 2
            for (int c = 0; c < CC; c++) {
                float xv[8], yv[14];
#pragma unroll
                for (int j = 0; j < 8; j++) xv[j] = xr[j];
#pragma unroll
                for (int t = 0; t < 14; t++) yv[t] = yr[yoff[t]];

                ull px[4], py[13];
#pragma unroll
                for (int j = 0; j < 4; j++) px[j] = pk(xv[2 * j], xv[2 * j + 1]);
#pragma unroll
                for (int t = 0; t < 13; t++) py[t] = pk(yv[t], yv[t + 1]);

#pragma unroll
                for (int i = 0; i < 7; i++)
#pragma unroll
                    for (int j = 0; j < 4; j++)
                        fma2(acc[i * 4 + j], px[j], py[2 * j + 6 - i]);

                xr += XSTRIDE; yr += YSTRIDE;
            }
        }
        __syncthreads();
    }

    // ---- store 7x8 tile ----
    if (active) {
#pragma unroll
        for (int i = 0; i < 7; i++) {
            const int d = d0 + i;
            float* o = out + (((long)b * D_DIM + d) * H_DIM + h) * W_DIM + w0;
            float2 p0 = upk(acc[i * 4 + 0]);
            float2 p1 = upk(acc[i * 4 + 1]);
            float2 p2 = upk(acc[i * 4 + 2]);
            float2 p3 = upk(acc[i * 4 + 3]);
            *reinterpret_cast<float4*>(o) = make_float4(p0.x, p0.y, p1.x, p1.y);
            *reinterpret_cast<float4*>(o + 4) = make_float4(p2.x, p2.y, p3.x, p3.y);
        }
    }
}

extern "C" void kernel_launch(void* const* d_in, const int* in_sizes, int n_in,
                              void* d_out, int out_size) {
    const float* x = (const float*)d_in[0];
    const float* y = (const float*)d_in[1];
    float* out = (float*)d_out;

    cudaFuncSetAttribute(coex_cost_kernel,
                         cudaFuncAttributeMaxDynamicSharedMemorySize, SMEM_BYTES);

    coex_cost_kernel<<<B_DIM * H_DIM, NTHREADS, SMEM_BYTES>>>(x, y, out);
}